// round 4
// baseline (speedup 1.0000x reference)
#include <cuda_runtime.h>
#include <cstdint>

// LocalConvolution: out[b,o,i,j] = sum_{c,u,v} x[b,c,i+u,j+v] * w[i,j,o,c,u,v]
// B=64, C=64, H=W=32, ROWS=COLS=28, O=128, KH=KW=5.
//
// One CTA per output pixel (784 CTAs, 128 threads). Per-channel K-chunks of 25,
// double-buffered in smem via cp.async (LDGSTS). Per thread: 8(b) x 8(o)
// register tile as 32 packed f32x2 accumulators updated with fma.rn.f32x2
// (2x fp32 FMA throughput vs scalar FFMA; only reachable via PTX).
// Audited R3: cp.async group accounting, bank conflicts, indexing, occupancy.

#define BATCH 64
#define CH    64
#define HH    32
#define WW    32
#define ROWS  28
#define COLS  28
#define OUT_O 128
#define KH    5
#define KW    5
#define KK    25          // KH*KW, K-chunk per channel
#define NPIX  784         // ROWS*COLS
#define KTOT  1600        // CH*KK

__device__ __forceinline__ void ffma2(unsigned long long& d,
                                      unsigned long long a,
                                      unsigned long long b) {
    asm("fma.rn.f32x2 %0, %1, %2, %0;" : "+l"(d) : "l"(a), "l"(b));
}

__device__ __forceinline__ unsigned long long dup2(float a) {
    unsigned long long d;
    asm("mov.b64 %0, {%1, %1};" : "=l"(d) : "f"(a));
    return d;
}

__device__ __forceinline__ void cp4(void* smem_dst, const float* gmem_src) {
    unsigned saddr = (unsigned)__cvta_generic_to_shared(smem_dst);
    asm volatile("cp.async.ca.shared.global [%0], [%1], 4;"
                 :: "r"(saddr), "l"(gmem_src));
}

__device__ __forceinline__ void stcs(float* p, float v) {
    asm volatile("st.global.cs.f32 [%0], %1;" :: "l"(p), "f"(v));
}

__global__ __launch_bounds__(128) void lconv_kernel(
    const float* __restrict__ x,
    const float* __restrict__ w,
    float* __restrict__ out)
{
    // sW[buf][k][o]: W chunk transposed so (o, o+1) pairs are 8B-contiguous.
    __shared__ float sW[2][KK][OUT_O];   // 25.0 KB
    // sA[buf][b][k]: scalar x window values (packed to f32x2 at use).
    __shared__ float sA[2][BATCH][KK];   // 12.5 KB

    const int p  = blockIdx.x;           // pixel id
    const int pi = p / COLS;
    const int pj = p % COLS;
    const int t  = threadIdx.x;          // 0..127
    const int tx = t & 15;               // o-pair lane (0..15)
    const int ty = t >> 4;               // b lane      (0..7)

    unsigned long long acc[8][4];        // [bb][pp] -> (o, o+1) pair
#pragma unroll
    for (int bb = 0; bb < 8; bb++)
#pragma unroll
        for (int pp = 0; pp < 4; pp++) acc[bb][pp] = 0ULL;

    const float* wp = w + (size_t)p * OUT_O * KTOT;   // weight[pi][pj][...]

    // ---- prefetch of one channel chunk into buffer 'buf' ----
#define PREFETCH(c, buf)                                                      \
    do {                                                                      \
        _Pragma("unroll 1")                                                   \
        for (int e = t; e < OUT_O * KK; e += 128) {                           \
            int o = e / KK;                                                   \
            int k = e - o * KK;                                               \
            cp4(&sW[buf][k][o], wp + (size_t)o * KTOT + (c) * KK + k);        \
        }                                                                     \
        _Pragma("unroll 1")                                                   \
        for (int e = t; e < BATCH * KK; e += 128) {                           \
            int b = e / KK;                                                   \
            int k = e - b * KK;                                               \
            int u = k / KW;                                                   \
            int v = k - u * KW;                                               \
            cp4(&sA[buf][b][k],                                               \
                x + (((size_t)b * CH + (c)) * HH + (pi + u)) * WW + (pj + v));\
        }                                                                     \
        asm volatile("cp.async.commit_group;");                               \
    } while (0)

    PREFETCH(0, 0);

    for (int c = 0; c < CH; c++) {
        const int cur = c & 1;
        if (c + 1 < CH) {
            PREFETCH(c + 1, cur ^ 1);
            asm volatile("cp.async.wait_group 1;");  // chunk c complete
        } else {
            asm volatile("cp.async.wait_group 0;");
        }
        __syncthreads();   // chunk c data visible to all

#pragma unroll
        for (int k = 0; k < KK; k++) {
            unsigned long long a2[8];
#pragma unroll
            for (int bb = 0; bb < 8; bb++)
                a2[bb] = dup2(sA[cur][ty + 8 * bb][k]);
#pragma unroll
            for (int pp = 0; pp < 4; pp++) {
                unsigned long long w2 =
                    *(const unsigned long long*)&sW[cur][k][2 * tx + 32 * pp];
#pragma unroll
                for (int bb = 0; bb < 8; bb++)
                    ffma2(acc[bb][pp], a2[bb], w2);
            }
        }
        __syncthreads();   // all reads of buf 'cur' done before it is refilled
    }

    // ---- epilogue: out[((b*128 + o)*784) + p], streaming stores ----
#pragma unroll
    for (int bb = 0; bb < 8; bb++) {
        int b = ty + 8 * bb;
#pragma unroll
        for (int pp = 0; pp < 4; pp++) {
            int o = 2 * tx + 32 * pp;
            unsigned long long a = acc[bb][pp];
            float lo = __uint_as_float((unsigned)(a & 0xffffffffULL));
            float hi = __uint_as_float((unsigned)(a >> 32));
            stcs(out + ((size_t)b * OUT_O + o)     * NPIX + p, lo);
            stcs(out + ((size_t)b * OUT_O + o + 1) * NPIX + p, hi);
        }
    }
}

extern "C" void kernel_launch(void* const* d_in, const int* in_sizes, int n_in,
                              void* d_out, int out_size) {
    const float* x = (const float*)d_in[0];   // [64,64,32,32]
    const float* w = (const float*)d_in[1];   // [28,28,128,64,5,5]
    float* out = (float*)d_out;               // [64,128,28,28]
    (void)in_sizes; (void)n_in; (void)out_size;
    lconv_kernel<<<NPIX, 128>>>(x, w, out);
}